// round 1
// baseline (speedup 1.0000x reference)
#include <cuda_runtime.h>
#include <cstdint>

#define NMAX 50048
#define GNUM 512

// ---------------- scratch (device globals; no runtime allocation) -------------
__device__ __align__(16) float g_deg[NMAX];
__device__ __align__(16) float g_dis[NMAX];
__device__ __align__(16) float g_h0[NMAX * 128];    // x @ W1
__device__ __align__(16) float g_agg1[NMAX * 128];  // neighbor agg conv1
__device__ __align__(16) float g_h[NMAX * 128];     // relu(conv1)
__device__ __align__(16) float g_hw[NMAX * 128];    // h @ [W3|W4]
__device__ __align__(16) float g_agg2[NMAX * 128];  // neighbor agg conv2 (both heads)
__device__ __align__(16) float g_Wc[128 * 128];     // [W3 | W4]
__device__ __align__(16) float g_sums[GNUM * 64];
__device__ float g_counts[GNUM];

// ---------------- init ----------------
__global__ void k_init(int N) {
    int i = blockIdx.x * blockDim.x + threadIdx.x;
    int tot = N * 128;
    if (i >= tot) return;
    g_agg1[i] = 0.f;
    g_agg2[i] = 0.f;
    if (i < N) g_deg[i] = 1.f;               // self-loop degree
    if (i < GNUM * 64) g_sums[i] = 0.f;
    if (i < GNUM) g_counts[i] = 0.f;
}

// ---------------- degree + rsqrt ----------------
__global__ void k_deg(const int* __restrict__ dst, int E) {
    int e = blockIdx.x * blockDim.x + threadIdx.x;
    if (e < E) atomicAdd(&g_deg[dst[e]], 1.f);
}

__global__ void k_rsqrt(int N) {
    int i = blockIdx.x * blockDim.x + threadIdx.x;
    if (i < N) g_dis[i] = rsqrtf(g_deg[i]);
}

// ---------------- GEMM: C[N,128] = A[N,K] @ B[K,128], K multiple of 32 -------
// block: 256 threads, tile 64 rows x 128 cols; per-thread 4x8 register tile.
__global__ void k_gemm128(const float* __restrict__ A, const float* __restrict__ B,
                          float* __restrict__ C, int N, int K) {
    __shared__ float As[32][65];    // [k][row], padded
    __shared__ float Bs[32][128];   // [k][col]

    int tid = threadIdx.x;
    int tx = tid & 15;              // col group (8 cols)
    int ty = tid >> 4;              // row group (4 rows)
    int row0 = blockIdx.x * 64;

    float acc[4][8];
#pragma unroll
    for (int i = 0; i < 4; i++)
#pragma unroll
        for (int j = 0; j < 8; j++) acc[i][j] = 0.f;

    for (int k0 = 0; k0 < K; k0 += 32) {
        // load A tile: 64 rows x 32 k  (8 elems/thread, coalesced)
#pragma unroll
        for (int i = 0; i < 8; i++) {
            int idx = i * 256 + tid;
            int n = idx >> 5, k = idx & 31;
            int r = row0 + n;
            As[k][n] = (r < N) ? A[(size_t)r * K + k0 + k] : 0.f;
        }
        // load B tile: 32 k x 128 cols (16 elems/thread, coalesced)
#pragma unroll
        for (int i = 0; i < 16; i++) {
            int idx = i * 256 + tid;
            int k = idx >> 7, c = idx & 127;
            Bs[k][c] = B[(size_t)(k0 + k) * 128 + c];
        }
        __syncthreads();

#pragma unroll
        for (int k = 0; k < 32; k++) {
            float a0 = As[k][ty * 4 + 0];
            float a1 = As[k][ty * 4 + 1];
            float a2 = As[k][ty * 4 + 2];
            float a3 = As[k][ty * 4 + 3];
            float4 b0 = *(const float4*)&Bs[k][tx * 8];
            float4 b1 = *(const float4*)&Bs[k][tx * 8 + 4];
            float bb[8] = {b0.x, b0.y, b0.z, b0.w, b1.x, b1.y, b1.z, b1.w};
            float aa[4] = {a0, a1, a2, a3};
#pragma unroll
            for (int i = 0; i < 4; i++)
#pragma unroll
                for (int j = 0; j < 8; j++) acc[i][j] = fmaf(aa[i], bb[j], acc[i][j]);
        }
        __syncthreads();
    }

#pragma unroll
    for (int i = 0; i < 4; i++) {
        int r = row0 + ty * 4 + i;
        if (r < N) {
            float4 o0 = make_float4(acc[i][0], acc[i][1], acc[i][2], acc[i][3]);
            float4 o1 = make_float4(acc[i][4], acc[i][5], acc[i][6], acc[i][7]);
            *(float4*)&C[(size_t)r * 128 + tx * 8] = o0;
            *(float4*)&C[(size_t)r * 128 + tx * 8 + 4] = o1;
        }
    }
}

// ---------------- edge scatter: agg[dst] += h[src] * (dis[src]*dis[dst]) ------
// one warp per edge; lane l handles floats [4l, 4l+4)
__global__ void k_scatter(const int* __restrict__ src, const int* __restrict__ dst,
                          const float* __restrict__ hs, float* __restrict__ agg, int E) {
    int gtid = blockIdx.x * blockDim.x + threadIdx.x;
    int e = gtid >> 5;
    int lane = gtid & 31;
    if (e >= E) return;
    int s = src[e];
    int d = dst[e];
    float nrm = g_dis[s] * g_dis[d];
    float4 v = *(const float4*)(hs + (size_t)s * 128 + lane * 4);
    v.x *= nrm; v.y *= nrm; v.z *= nrm; v.w *= nrm;
    float* a = agg + (size_t)d * 128 + lane * 4;
    asm volatile("red.global.add.v4.f32 [%0], {%1,%2,%3,%4};"
                 :: "l"(a), "f"(v.x), "f"(v.y), "f"(v.z), "f"(v.w)
                 : "memory");
}

// ---------------- conv1 epilogue: h = relu(agg1 + h0*dis^2 + b1) --------------
__global__ void k_act1(const float* __restrict__ b1, int N) {
    int i = blockIdx.x * blockDim.x + threadIdx.x;   // over N*32 float4 chunks
    if (i >= N * 32) return;
    int node = i >> 5;
    int c = (i & 31) * 4;
    float d = g_dis[node];
    float d2 = d * d;
    float4 a = *(float4*)&g_agg1[(size_t)i * 4];
    float4 h0 = *(float4*)&g_h0[(size_t)i * 4];
    float4 b = *(const float4*)&b1[c];
    float4 r;
    r.x = fmaxf(fmaf(h0.x, d2, a.x) + b.x, 0.f);
    r.y = fmaxf(fmaf(h0.y, d2, a.y) + b.y, 0.f);
    r.z = fmaxf(fmaf(h0.z, d2, a.z) + b.z, 0.f);
    r.w = fmaxf(fmaf(h0.w, d2, a.w) + b.w, 0.f);
    *(float4*)&g_h[(size_t)i * 4] = r;
}

// ---------------- build fused weight [W3 | W4] --------------------------------
__global__ void k_wc(const float* __restrict__ W3, const float* __restrict__ W4) {
    int i = blockIdx.x * blockDim.x + threadIdx.x;   // 128*64
    if (i >= 128 * 64) return;
    int k = i >> 6, c = i & 63;
    g_Wc[k * 128 + c] = W3[i];
    g_Wc[k * 128 + 64 + c] = W4[i];
}

// ---------------- conv2 epilogue + reparam + pooled scatter -------------------
__global__ void k_final(const float* __restrict__ b3, const float* __restrict__ b4,
                        const float* __restrict__ noise, const int* __restrict__ batch,
                        int N) {
    int i = blockIdx.x * blockDim.x + threadIdx.x;   // N*16 float4 chunks of z
    if (i >= N * 16) return;
    int node = i >> 4;
    int c = (i & 15) * 4;
    float d = g_dis[node];
    float d2 = d * d;
    int g = batch[node];
    float4 am = *(float4*)&g_agg2[(size_t)node * 128 + c];
    float4 hm = *(float4*)&g_hw[(size_t)node * 128 + c];
    float4 as = *(float4*)&g_agg2[(size_t)node * 128 + 64 + c];
    float4 hsv = *(float4*)&g_hw[(size_t)node * 128 + 64 + c];
    float4 B3 = *(const float4*)&b3[c];
    float4 B4 = *(const float4*)&b4[c];
    float4 nz = *(const float4*)&noise[(size_t)node * 64 + c];
    float4 z;
    z.x = (fmaf(hm.x, d2, am.x) + B3.x) + nz.x * expf(fmaf(hsv.x, d2, as.x) + B4.x);
    z.y = (fmaf(hm.y, d2, am.y) + B3.y) + nz.y * expf(fmaf(hsv.y, d2, as.y) + B4.y);
    z.z = (fmaf(hm.z, d2, am.z) + B3.z) + nz.z * expf(fmaf(hsv.z, d2, as.z) + B4.z);
    z.w = (fmaf(hm.w, d2, am.w) + B3.w) + nz.w * expf(fmaf(hsv.w, d2, as.w) + B4.w);
    float* sp = &g_sums[g * 64 + c];
    asm volatile("red.global.add.v4.f32 [%0], {%1,%2,%3,%4};"
                 :: "l"(sp), "f"(z.x), "f"(z.y), "f"(z.z), "f"(z.w)
                 : "memory");
    if ((i & 15) == 0) atomicAdd(&g_counts[g], 1.f);
}

// ---------------- head: pooled @ Wfc + bfc, log_softmax -----------------------
__global__ void k_head(const float* __restrict__ Wfc, const float* __restrict__ bfc,
                       float* __restrict__ out) {
    int g = blockIdx.x * blockDim.x + threadIdx.x;
    if (g >= GNUM) return;
    float inv = 1.f / fmaxf(g_counts[g], 1.f);
    float l0 = bfc[0], l1 = bfc[1], l2 = bfc[2], l3 = bfc[3];
#pragma unroll
    for (int k = 0; k < 64; k++) {
        float p = g_sums[g * 64 + k] * inv;
        l0 = fmaf(p, Wfc[k * 4 + 0], l0);
        l1 = fmaf(p, Wfc[k * 4 + 1], l1);
        l2 = fmaf(p, Wfc[k * 4 + 2], l2);
        l3 = fmaf(p, Wfc[k * 4 + 3], l3);
    }
    float m = fmaxf(fmaxf(l0, l1), fmaxf(l2, l3));
    float s = expf(l0 - m) + expf(l1 - m) + expf(l2 - m) + expf(l3 - m);
    float lse = m + logf(s);
    out[g * 4 + 0] = l0 - lse;
    out[g * 4 + 1] = l1 - lse;
    out[g * 4 + 2] = l2 - lse;
    out[g * 4 + 3] = l3 - lse;
}

// ---------------- launch -------------------------------------------------------
extern "C" void kernel_launch(void* const* d_in, const int* in_sizes, int n_in,
                              void* d_out, int out_size) {
    const float* x     = (const float*)d_in[0];
    const int*   ei    = (const int*)d_in[1];
    const int*   batch = (const int*)d_in[2];
    const float* W1    = (const float*)d_in[3];
    const float* b1    = (const float*)d_in[4];
    const float* W3    = (const float*)d_in[5];
    const float* b3    = (const float*)d_in[6];
    const float* W4    = (const float*)d_in[7];
    const float* b4    = (const float*)d_in[8];
    const float* Wfc   = (const float*)d_in[9];
    const float* bfc   = (const float*)d_in[10];
    const float* noise = (const float*)d_in[11];
    float* out = (float*)d_out;

    int N = in_sizes[2];        // 50000
    int E = in_sizes[1] / 2;    // 800000
    const int* src = ei;
    const int* dst = ei + E;

    float *h0p, *agg1p, *hp, *hwp, *agg2p, *Wcp;
    cudaGetSymbolAddress((void**)&h0p, g_h0);
    cudaGetSymbolAddress((void**)&agg1p, g_agg1);
    cudaGetSymbolAddress((void**)&hp, g_h);
    cudaGetSymbolAddress((void**)&hwp, g_hw);
    cudaGetSymbolAddress((void**)&agg2p, g_agg2);
    cudaGetSymbolAddress((void**)&Wcp, g_Wc);

    int tot = N * 128;
    k_init<<<(tot + 255) / 256, 256>>>(N);
    k_deg<<<(E + 255) / 256, 256>>>(dst, E);
    k_rsqrt<<<(N + 255) / 256, 256>>>(N);

    // conv1
    k_gemm128<<<(N + 63) / 64, 256>>>(x, W1, h0p, N, 256);
    {
        long long t = (long long)E * 32;
        k_scatter<<<(unsigned)((t + 255) / 256), 256>>>(src, dst, h0p, agg1p, E);
    }
    k_act1<<<(N * 32 + 255) / 256, 256>>>(b1, N);

    // conv2 (mean || log_std fused)
    k_wc<<<(128 * 64 + 255) / 256, 256>>>(W3, W4);
    k_gemm128<<<(N + 63) / 64, 256>>>(hp, Wcp, hwp, N, 128);
    {
        long long t = (long long)E * 32;
        k_scatter<<<(unsigned)((t + 255) / 256), 256>>>(src, dst, hwp, agg2p, E);
    }

    // reparam + pool
    k_final<<<(N * 16 + 255) / 256, 256>>>(b3, b4, noise, batch, N);

    // head
    k_head<<<(GNUM + 255) / 256, 256>>>(Wfc, bfc, out);
}

// round 2
// speedup vs baseline: 1.0478x; 1.0478x over previous
#include <cuda_runtime.h>
#include <cstdint>

#define NMAX 50048
#define GNUM 512

// ---------------- scratch (device globals; no runtime allocation) -------------
__device__ __align__(16) float g_deg[NMAX];
__device__ __align__(16) float g_dis[NMAX];
__device__ __align__(16) float g_h0[NMAX * 128];    // x @ W1
__device__ __align__(16) float g_agg1[NMAX * 128];  // neighbor agg conv1
__device__ __align__(16) float g_h[NMAX * 128];     // relu(conv1)
__device__ __align__(16) float g_hw[NMAX * 128];    // h @ [W3|W4]
__device__ __align__(16) float g_agg2[NMAX * 128];  // neighbor agg conv2 (both heads)
__device__ __align__(16) float g_Wc[128 * 128];     // [W3 | W4]
__device__ __align__(16) float g_sums[GNUM * 64];
__device__ float g_counts[GNUM];

// ---------------- init ----------------
__global__ void k_init(int N) {
    int i = blockIdx.x * blockDim.x + threadIdx.x;
    int tot = N * 128;
    if (i >= tot) return;
    g_agg1[i] = 0.f;
    g_agg2[i] = 0.f;
    if (i < N) g_deg[i] = 1.f;               // self-loop degree
    if (i < GNUM * 64) g_sums[i] = 0.f;
    if (i < GNUM) g_counts[i] = 0.f;
}

// ---------------- degree + rsqrt ----------------
__global__ void k_deg(const int* __restrict__ dst, int E) {
    int e = blockIdx.x * blockDim.x + threadIdx.x;
    if (e < E) atomicAdd(&g_deg[dst[e]], 1.f);
}

__global__ void k_rsqrt(int N) {
    int i = blockIdx.x * blockDim.x + threadIdx.x;
    if (i < N) g_dis[i] = rsqrtf(g_deg[i]);
}

// ---------------- GEMM: C[N,128] = A[N,K] @ B[K,128], K multiple of 16 -------
// 128x128 block tile, 256 threads, 8x8 per-thread register tile, K-chunk 16.
// A stored transposed in smem (As[k][row]); global loads register-prefetched.
__global__ void __launch_bounds__(256, 2)
k_gemm128(const float* __restrict__ A, const float* __restrict__ B,
          float* __restrict__ C, int N, int K) {
    __shared__ float As[16][128];   // [k][row]
    __shared__ float Bs[16][128];   // [k][col]

    int tid = threadIdx.x;
    int tr = tid >> 4;              // 0..15 : row group (8 rows)
    int tc = tid & 15;              // 0..15 : col group (8 cols)
    int row0 = blockIdx.x * 128;

    float acc[8][8];
#pragma unroll
    for (int i = 0; i < 8; i++)
#pragma unroll
        for (int j = 0; j < 8; j++) acc[i][j] = 0.f;

    // prefetch registers: A tile = 128 rows x 16 k = 512 float4, 2/thread
    //                     B tile = 16 k x 128 cols = 512 float4, 2/thread
    float4 pa[2], pb[2];
    int a_row[2], a_kq[2], b_k[2], b_c[2];
#pragma unroll
    for (int i = 0; i < 2; i++) {
        int idx = tid + i * 256;
        a_row[i] = idx >> 2;        // 0..127
        a_kq[i]  = (idx & 3) * 4;   // 0,4,8,12
        b_k[i]   = idx >> 5;        // 0..15
        b_c[i]   = (idx & 31) * 4;  // 0..124
    }

    auto load_chunk = [&](int k0) {
#pragma unroll
        for (int i = 0; i < 2; i++) {
            int r = row0 + a_row[i];
            pa[i] = (r < N) ? *(const float4*)&A[(size_t)r * K + k0 + a_kq[i]]
                            : make_float4(0.f, 0.f, 0.f, 0.f);
            pb[i] = *(const float4*)&B[(size_t)(k0 + b_k[i]) * 128 + b_c[i]];
        }
    };

    load_chunk(0);
    int nchunks = K >> 4;

    for (int ch = 0; ch < nchunks; ch++) {
        __syncthreads();
#pragma unroll
        for (int i = 0; i < 2; i++) {
            // transpose A into smem
            As[a_kq[i] + 0][a_row[i]] = pa[i].x;
            As[a_kq[i] + 1][a_row[i]] = pa[i].y;
            As[a_kq[i] + 2][a_row[i]] = pa[i].z;
            As[a_kq[i] + 3][a_row[i]] = pa[i].w;
            *(float4*)&Bs[b_k[i]][b_c[i]] = pb[i];
        }
        __syncthreads();

        if (ch + 1 < nchunks) load_chunk((ch + 1) << 4);

#pragma unroll
        for (int k = 0; k < 16; k++) {
            float4 a0 = *(const float4*)&As[k][tr * 8];
            float4 a1 = *(const float4*)&As[k][tr * 8 + 4];
            float4 b0 = *(const float4*)&Bs[k][tc * 8];
            float4 b1 = *(const float4*)&Bs[k][tc * 8 + 4];
            float av[8] = {a0.x, a0.y, a0.z, a0.w, a1.x, a1.y, a1.z, a1.w};
            float bv[8] = {b0.x, b0.y, b0.z, b0.w, b1.x, b1.y, b1.z, b1.w};
#pragma unroll
            for (int i = 0; i < 8; i++)
#pragma unroll
                for (int j = 0; j < 8; j++)
                    acc[i][j] = fmaf(av[i], bv[j], acc[i][j]);
        }
    }

#pragma unroll
    for (int i = 0; i < 8; i++) {
        int r = row0 + tr * 8 + i;
        if (r < N) {
            float4 o0 = make_float4(acc[i][0], acc[i][1], acc[i][2], acc[i][3]);
            float4 o1 = make_float4(acc[i][4], acc[i][5], acc[i][6], acc[i][7]);
            *(float4*)&C[(size_t)r * 128 + tc * 8] = o0;
            *(float4*)&C[(size_t)r * 128 + tc * 8 + 4] = o1;
        }
    }
}

// ---------------- edge scatter: agg[dst] += h[src] * (dis[src]*dis[dst]) ------
// one warp per edge; lane l handles floats [4l, 4l+4)
__global__ void k_scatter(const int* __restrict__ src, const int* __restrict__ dst,
                          const float* __restrict__ hs, float* __restrict__ agg, int E) {
    int gtid = blockIdx.x * blockDim.x + threadIdx.x;
    int e = gtid >> 5;
    int lane = gtid & 31;
    if (e >= E) return;
    int s = src[e];
    int d = dst[e];
    float nrm = g_dis[s] * g_dis[d];
    float4 v = *(const float4*)(hs + (size_t)s * 128 + lane * 4);
    v.x *= nrm; v.y *= nrm; v.z *= nrm; v.w *= nrm;
    float* a = agg + (size_t)d * 128 + lane * 4;
    asm volatile("red.global.add.v4.f32 [%0], {%1,%2,%3,%4};"
                 :: "l"(a), "f"(v.x), "f"(v.y), "f"(v.z), "f"(v.w)
                 : "memory");
}

// ---------------- conv1 epilogue: h = relu(agg1 + h0*dis^2 + b1) --------------
__global__ void k_act1(const float* __restrict__ b1, int N) {
    int i = blockIdx.x * blockDim.x + threadIdx.x;   // over N*32 float4 chunks
    if (i >= N * 32) return;
    int node = i >> 5;
    int c = (i & 31) * 4;
    float d = g_dis[node];
    float d2 = d * d;
    float4 a = *(float4*)&g_agg1[(size_t)i * 4];
    float4 h0 = *(float4*)&g_h0[(size_t)i * 4];
    float4 b = *(const float4*)&b1[c];
    float4 r;
    r.x = fmaxf(fmaf(h0.x, d2, a.x) + b.x, 0.f);
    r.y = fmaxf(fmaf(h0.y, d2, a.y) + b.y, 0.f);
    r.z = fmaxf(fmaf(h0.z, d2, a.z) + b.z, 0.f);
    r.w = fmaxf(fmaf(h0.w, d2, a.w) + b.w, 0.f);
    *(float4*)&g_h[(size_t)i * 4] = r;
}

// ---------------- build fused weight [W3 | W4] --------------------------------
__global__ void k_wc(const float* __restrict__ W3, const float* __restrict__ W4) {
    int i = blockIdx.x * blockDim.x + threadIdx.x;   // 128*64
    if (i >= 128 * 64) return;
    int k = i >> 6, c = i & 63;
    g_Wc[k * 128 + c] = W3[i];
    g_Wc[k * 128 + 64 + c] = W4[i];
}

// ---------------- conv2 epilogue + reparam + pooled scatter -------------------
__global__ void k_final(const float* __restrict__ b3, const float* __restrict__ b4,
                        const float* __restrict__ noise, const int* __restrict__ batch,
                        int N) {
    int i = blockIdx.x * blockDim.x + threadIdx.x;   // N*16 float4 chunks of z
    if (i >= N * 16) return;
    int node = i >> 4;
    int c = (i & 15) * 4;
    float d = g_dis[node];
    float d2 = d * d;
    int g = batch[node];
    float4 am = *(float4*)&g_agg2[(size_t)node * 128 + c];
    float4 hm = *(float4*)&g_hw[(size_t)node * 128 + c];
    float4 as = *(float4*)&g_agg2[(size_t)node * 128 + 64 + c];
    float4 hsv = *(float4*)&g_hw[(size_t)node * 128 + 64 + c];
    float4 B3 = *(const float4*)&b3[c];
    float4 B4 = *(const float4*)&b4[c];
    float4 nz = *(const float4*)&noise[(size_t)node * 64 + c];
    float4 z;
    z.x = (fmaf(hm.x, d2, am.x) + B3.x) + nz.x * expf(fmaf(hsv.x, d2, as.x) + B4.x);
    z.y = (fmaf(hm.y, d2, am.y) + B3.y) + nz.y * expf(fmaf(hsv.y, d2, as.y) + B4.y);
    z.z = (fmaf(hm.z, d2, am.z) + B3.z) + nz.z * expf(fmaf(hsv.z, d2, as.z) + B4.z);
    z.w = (fmaf(hm.w, d2, am.w) + B3.w) + nz.w * expf(fmaf(hsv.w, d2, as.w) + B4.w);
    float* sp = &g_sums[g * 64 + c];
    asm volatile("red.global.add.v4.f32 [%0], {%1,%2,%3,%4};"
                 :: "l"(sp), "f"(z.x), "f"(z.y), "f"(z.z), "f"(z.w)
                 : "memory");
    if ((i & 15) == 0) atomicAdd(&g_counts[g], 1.f);
}

// ---------------- head: pooled @ Wfc + bfc, log_softmax -----------------------
__global__ void k_head(const float* __restrict__ Wfc, const float* __restrict__ bfc,
                       float* __restrict__ out) {
    int g = blockIdx.x * blockDim.x + threadIdx.x;
    if (g >= GNUM) return;
    float inv = 1.f / fmaxf(g_counts[g], 1.f);
    float l0 = bfc[0], l1 = bfc[1], l2 = bfc[2], l3 = bfc[3];
#pragma unroll
    for (int k = 0; k < 64; k++) {
        float p = g_sums[g * 64 + k] * inv;
        l0 = fmaf(p, Wfc[k * 4 + 0], l0);
        l1 = fmaf(p, Wfc[k * 4 + 1], l1);
        l2 = fmaf(p, Wfc[k * 4 + 2], l2);
        l3 = fmaf(p, Wfc[k * 4 + 3], l3);
    }
    float m = fmaxf(fmaxf(l0, l1), fmaxf(l2, l3));
    float s = expf(l0 - m) + expf(l1 - m) + expf(l2 - m) + expf(l3 - m);
    float lse = m + logf(s);
    out[g * 4 + 0] = l0 - lse;
    out[g * 4 + 1] = l1 - lse;
    out[g * 4 + 2] = l2 - lse;
    out[g * 4 + 3] = l3 - lse;
}

// ---------------- launch -------------------------------------------------------
extern "C" void kernel_launch(void* const* d_in, const int* in_sizes, int n_in,
                              void* d_out, int out_size) {
    const float* x     = (const float*)d_in[0];
    const int*   ei    = (const int*)d_in[1];
    const int*   batch = (const int*)d_in[2];
    const float* W1    = (const float*)d_in[3];
    const float* b1    = (const float*)d_in[4];
    const float* W3    = (const float*)d_in[5];
    const float* b3    = (const float*)d_in[6];
    const float* W4    = (const float*)d_in[7];
    const float* b4    = (const float*)d_in[8];
    const float* Wfc   = (const float*)d_in[9];
    const float* bfc   = (const float*)d_in[10];
    const float* noise = (const float*)d_in[11];
    float* out = (float*)d_out;

    int N = in_sizes[2];        // 50000
    int E = in_sizes[1] / 2;    // 800000
    const int* src = ei;
    const int* dst = ei + E;

    float *h0p, *agg1p, *hp, *hwp, *agg2p, *Wcp;
    cudaGetSymbolAddress((void**)&h0p, g_h0);
    cudaGetSymbolAddress((void**)&agg1p, g_agg1);
    cudaGetSymbolAddress((void**)&hp, g_h);
    cudaGetSymbolAddress((void**)&hwp, g_hw);
    cudaGetSymbolAddress((void**)&agg2p, g_agg2);
    cudaGetSymbolAddress((void**)&Wcp, g_Wc);

    int tot = N * 128;
    k_init<<<(tot + 255) / 256, 256>>>(N);
    k_deg<<<(E + 255) / 256, 256>>>(dst, E);
    k_rsqrt<<<(N + 255) / 256, 256>>>(N);

    // conv1
    k_gemm128<<<(N + 127) / 128, 256>>>(x, W1, h0p, N, 256);
    {
        long long t = (long long)E * 32;
        k_scatter<<<(unsigned)((t + 255) / 256), 256>>>(src, dst, h0p, agg1p, E);
    }
    k_act1<<<(N * 32 + 255) / 256, 256>>>(b1, N);

    // conv2 (mean || log_std fused)
    k_wc<<<(128 * 64 + 255) / 256, 256>>>(W3, W4);
    k_gemm128<<<(N + 127) / 128, 256>>>(hp, Wcp, hwp, N, 128);
    {
        long long t = (long long)E * 32;
        k_scatter<<<(unsigned)((t + 255) / 256), 256>>>(src, dst, hwp, agg2p, E);
    }

    // reparam + pool
    k_final<<<(N * 16 + 255) / 256, 256>>>(b3, b4, noise, batch, N);

    // head
    k_head<<<(GNUM + 255) / 256, 256>>>(Wfc, bfc, out);
}